// round 3
// baseline (speedup 1.0000x reference)
#include <cuda_runtime.h>

#define BB 64
#define SZ 2048
#define LL 16
#define AA 64
#define HH 256
#define RR 65536
#define XW (SZ + LL)

// ---------------- scratch (static device globals; no allocs) ----------------
__device__ __align__(16) float g_P1[SZ * HH];
__device__ __align__(16) float g_P2[SZ * HH];
__device__ __align__(16) float g_rel[RR * AA];        // relation rows, CSR-sorted order
__device__ __align__(16) float g_metaT[LL * AA * BB]; // [t][k][b]
__device__ __align__(16) float g_state[2][SZ * BB];   // [o][b], double buffered
__device__ int g_perm[RR];
__device__ int g_subjS[RR];
__device__ int g_objS[RR];
__device__ int g_counts[SZ];
__device__ int g_rowptr[SZ + 1];
__device__ int g_offs[SZ];

// ---------------- CSR build (deterministic) ----------------
__global__ void k_zero() {
    int i = blockIdx.x * blockDim.x + threadIdx.x;
    if (i < SZ) g_counts[i] = 0;
}

__global__ void k_hist(const int* __restrict__ robj) {
    int e = blockIdx.x * blockDim.x + threadIdx.x;
    if (e < RR) atomicAdd(&g_counts[robj[e]], 1);
}

__global__ void k_scan() {  // 1 block, 1024 threads: scan of 2048
    __shared__ int sA[SZ], sB[SZ];
    int tid = threadIdx.x;
    for (int i = tid; i < SZ; i += 1024) sA[i] = g_counts[i];
    __syncthreads();
    int* src = sA; int* dst = sB;
    for (int off = 1; off < SZ; off <<= 1) {
        for (int i = tid; i < SZ; i += 1024)
            dst[i] = src[i] + (i >= off ? src[i - off] : 0);
        __syncthreads();
        int* t = src; src = dst; dst = t;
    }
    for (int i = tid; i < SZ; i += 1024) {
        g_rowptr[i + 1] = src[i];
        g_offs[i] = (i == 0) ? 0 : src[i - 1];
    }
    if (tid == 0) g_rowptr[0] = 0;
}

__global__ void k_scatter(const int* __restrict__ robj) {
    int e = blockIdx.x * blockDim.x + threadIdx.x;
    if (e < RR) {
        int pos = atomicAdd(&g_offs[robj[e]], 1);
        g_perm[pos] = e;
    }
}

// sort each bucket's edge ids ascending (determinism), emit subj/obj in sorted order
__global__ void k_bsort(const int* __restrict__ rsub) {
    __shared__ int buf[8][208];
    int wid = threadIdx.x >> 5, lane = threadIdx.x & 31;
    int o = blockIdx.x * 8 + wid;
    int s = g_rowptr[o], e = g_rowptr[o + 1], n = e - s;
    if (n > 0 && n <= 208) {
        for (int i = lane; i < n; i += 32) buf[wid][i] = g_perm[s + i];
        __syncwarp();
        for (int r = 0; r < n; r++) {           // odd-even transposition
            int par = r & 1;
            for (int i = par + 2 * lane; i + 1 < n; i += 64) {
                int a = buf[wid][i], b = buf[wid][i + 1];
                if (a > b) { buf[wid][i] = b; buf[wid][i + 1] = a; }
            }
            __syncwarp();
        }
        for (int i = lane; i < n; i += 32) {
            int p = buf[wid][i];
            g_perm[s + i] = p;
            g_subjS[s + i] = rsub[p];
            g_objS[s + i] = o;
        }
    } else {
        for (int i = lane; i < n; i += 32) {
            int p = g_perm[s + i];
            g_subjS[s + i] = rsub[p];
            g_objS[s + i] = o;
        }
    }
}

// ---------------- P1/P2 = state_emb @ W1 halves ----------------
__global__ void k_p12(const float* __restrict__ emb, const float* __restrict__ w1) {
    __shared__ float es[8][64];
    int tid = threadIdx.x;
    int r0 = blockIdx.x * 8;
    for (int i = tid; i < 512; i += 256) es[i >> 6][i & 63] = emb[r0 * 64 + i];
    __syncthreads();
    float a1[8], a2[8];
#pragma unroll
    for (int r = 0; r < 8; r++) { a1[r] = 0.f; a2[r] = 0.f; }
    for (int k = 0; k < 64; k++) {
        float wa = w1[k * HH + tid];
        float wb = w1[(64 + k) * HH + tid];
#pragma unroll
        for (int r = 0; r < 8; r++) {
            a1[r] += es[r][k] * wa;
            a2[r] += es[r][k] * wb;
        }
    }
#pragma unroll
    for (int r = 0; r < 8; r++) {
        g_P1[(r0 + r) * HH + tid] = a1[r];
        g_P2[(r0 + r) * HH + tid] = a2[r];
    }
}

// ---------------- relation rows (sorted order): relu(P1[s]+P2[o]+b1) @ W2 + b2
#define RELROWS 32
__global__ void k_rel(const float* __restrict__ b1v, const float* __restrict__ w2,
                      const float* __restrict__ b2v) {  // 2048 blocks x 128 threads
    __shared__ float hs[RELROWS][256];
    int base = blockIdx.x * RELROWS;
    int tid = threadIdx.x;
    for (int r = 0; r < RELROWS; r++) {
        int s = g_subjS[base + r], o = g_objS[base + r];
        for (int j = tid; j < 256; j += 128) {
            float v = g_P1[s * HH + j] + g_P2[o * HH + j] + b1v[j];
            hs[r][j] = fmaxf(v, 0.f);
        }
    }
    __syncthreads();
    int d0 = (tid & 15) * 4;
    int r0 = (tid >> 4) * 4;
    float4 a0 = {0,0,0,0}, a1 = {0,0,0,0}, a2 = {0,0,0,0}, a3 = {0,0,0,0};
    for (int k = 0; k < 256; k++) {
        float4 w = *(const float4*)&w2[k * 64 + d0];
        float h0 = hs[r0 + 0][k], h1 = hs[r0 + 1][k], h2 = hs[r0 + 2][k], h3 = hs[r0 + 3][k];
        a0.x += h0 * w.x; a0.y += h0 * w.y; a0.z += h0 * w.z; a0.w += h0 * w.w;
        a1.x += h1 * w.x; a1.y += h1 * w.y; a1.z += h1 * w.z; a1.w += h1 * w.w;
        a2.x += h2 * w.x; a2.y += h2 * w.y; a2.z += h2 * w.z; a2.w += h2 * w.w;
        a3.x += h3 * w.x; a3.y += h3 * w.y; a3.z += h3 * w.z; a3.w += h3 * w.w;
    }
    float4 bb = *(const float4*)&b2v[d0];
    a0.x += bb.x; a0.y += bb.y; a0.z += bb.z; a0.w += bb.w;
    a1.x += bb.x; a1.y += bb.y; a1.z += bb.z; a1.w += bb.w;
    a2.x += bb.x; a2.y += bb.y; a2.z += bb.z; a2.w += bb.w;
    a3.x += bb.x; a3.y += bb.y; a3.z += bb.z; a3.w += bb.w;
    *(float4*)&g_rel[(base + r0 + 0) * 64 + d0] = a0;
    *(float4*)&g_rel[(base + r0 + 1) * 64 + d0] = a1;
    *(float4*)&g_rel[(base + r0 + 2) * 64 + d0] = a2;
    *(float4*)&g_rel[(base + r0 + 3) * 64 + d0] = a3;
}

// ---------------- meta recurrence: 32 blocks x (2 batches x 128 threads) ----------------
__global__ void k_meta(const int* __restrict__ x, const float* __restrict__ aemb,
                       const float* __restrict__ pemb, const float* __restrict__ qw,
                       const float* __restrict__ qb, const float* __restrict__ mw1,
                       const float* __restrict__ mb1, const float* __restrict__ mw2,
                       const float* __restrict__ mb2, const float* __restrict__ minit) {
    __shared__ float sent[2][16][128];
    __shared__ float meta[2][64];
    __shared__ float query[2][128];
    __shared__ float attn[2][16];
    __shared__ float z[2][192];
    __shared__ float hid[2][256];
    int tid = threadIdx.x;
    int g = tid >> 7, t = tid & 127;
    int b = blockIdx.x * 2 + g;
    for (int l = 0; l < 16; l++) {
        int a = x[b * XW + SZ + l];
        sent[g][l][t] = (t < 64) ? aemb[a * 64 + t] : pemb[l * 64 + (t - 64)];
    }
    if (t < 64) meta[g][t] = minit[t];
    __syncthreads();
    for (int st = 0; st < 16; st++) {
        float q = qb[t];
        for (int k = 0; k < 64; k++) q += meta[g][k] * qw[k * 128 + t];
        query[g][t] = q;
        __syncthreads();
        if (t < 16) {
            float sc = 0.f;
            for (int d = 0; d < 128; d++) sc += query[g][d] * sent[g][t][d];
            attn[g][t] = sc;
        }
        __syncthreads();
        if (t == 0) {
            float m = attn[g][0];
            for (int l = 1; l < 16; l++) m = fmaxf(m, attn[g][l]);
            float ev[16], ssum = 0.f;
            for (int l = 0; l < 16; l++) { ev[l] = __expf(attn[g][l] - m); ssum += ev[l]; }
            for (int l = 0; l < 16; l++) attn[g][l] = ev[l] / ssum;
        }
        __syncthreads();
        {
            float at = 0.f;
            for (int l = 0; l < 16; l++) at += attn[g][l] * sent[g][l][t];
            z[g][64 + t] = at;
            if (t < 64) z[g][t] = meta[g][t];
        }
        __syncthreads();
        {
            float h0 = mb1[t], h1 = mb1[t + 128];
            for (int k = 0; k < 192; k++) {
                float zv = z[g][k];
                h0 += zv * mw1[k * HH + t];
                h1 += zv * mw1[k * HH + t + 128];
            }
            hid[g][t] = fmaxf(h0, 0.f);
            hid[g][t + 128] = fmaxf(h1, 0.f);
        }
        __syncthreads();
        if (t < 64) {
            float m = mb2[t];
            for (int k = 0; k < 256; k++) m += hid[g][k] * mw2[k * 64 + t];
            g_metaT[(st * 64 + t) * 64 + b] = m;  // [t][k][b]
            meta[g][t] = m;
        }
        __syncthreads();
    }
}

// ---------------- init transposed state ----------------
__global__ void k_init(const int* __restrict__ x) {
    int i = blockIdx.x * blockDim.x + threadIdx.x;  // 131072
    int b = i >> 11, o = i & 2047;
    g_state[0][o * 64 + b] = (float)x[b * XW + o];
}

__device__ __forceinline__ float sigf(float v) {
    return __fdividef(1.f, 1.f + __expf(-v));
}

// ---------------- one propagation step: warp-per-bucket, no atomics ----------------
__global__ void k_step(int t, float* __restrict__ out) {
    __shared__ __align__(16) float ms[64 * 64];   // meta [k][b]
    __shared__ __align__(16) float rs[8][8 * 64]; // 8-edge staging per warp
    __shared__ int sj[8][8];
    int tid = threadIdx.x, wid = tid >> 5, lane = tid & 31;
    const float* __restrict__ stIn = g_state[t & 1];
    float* __restrict__ stOut = g_state[(t + 1) & 1];
    const float* mt = &g_metaT[t * 4096];
    for (int i = tid; i < 4096; i += 256) ms[i] = mt[i];
    __syncthreads();
    int o = blockIdx.x * 8 + wid;
    int s0 = g_rowptr[o], s1 = g_rowptr[o + 1];
    int b0 = (lane & 15) << 2, eg = lane >> 4;
    float ac0 = 0.f, ac1 = 0.f, ac2 = 0.f, ac3 = 0.f;
    for (int base = s0; base < s1; base += 8) {
        int m = min(8, s1 - base);
        for (int i = lane; i < m * 64; i += 32) rs[wid][i] = g_rel[base * 64 + i];
        if (lane < m) sj[wid][lane] = g_subjS[base + lane];
        __syncwarp();
        int lo = eg * 4, hi = min(m, eg * 4 + 4);
        if (hi - lo == 4) {
            const float* r0 = &rs[wid][lo * 64];
            const float* r1 = r0 + 64;
            const float* r2 = r1 + 64;
            const float* r3 = r2 + 64;
            float4 s0v = *(const float4*)&stIn[sj[wid][lo + 0] * 64 + b0];
            float4 s1v = *(const float4*)&stIn[sj[wid][lo + 1] * 64 + b0];
            float4 s2v = *(const float4*)&stIn[sj[wid][lo + 2] * 64 + b0];
            float4 s3v = *(const float4*)&stIn[sj[wid][lo + 3] * 64 + b0];
            float4 d0 = {0,0,0,0}, d1 = {0,0,0,0}, d2 = {0,0,0,0}, d3 = {0,0,0,0};
#pragma unroll
            for (int k = 0; k < 64; k++) {
                float4 mv = *(const float4*)&ms[k * 64 + b0];
                float v0 = r0[k], v1 = r1[k], v2 = r2[k], v3 = r3[k];
                d0.x += mv.x * v0; d0.y += mv.y * v0; d0.z += mv.z * v0; d0.w += mv.w * v0;
                d1.x += mv.x * v1; d1.y += mv.y * v1; d1.z += mv.z * v1; d1.w += mv.w * v1;
                d2.x += mv.x * v2; d2.y += mv.y * v2; d2.z += mv.z * v2; d2.w += mv.w * v2;
                d3.x += mv.x * v3; d3.y += mv.y * v3; d3.z += mv.z * v3; d3.w += mv.w * v3;
            }
            ac0 += s0v.x * sigf(d0.x) + s1v.x * sigf(d1.x) + s2v.x * sigf(d2.x) + s3v.x * sigf(d3.x);
            ac1 += s0v.y * sigf(d0.y) + s1v.y * sigf(d1.y) + s2v.y * sigf(d2.y) + s3v.y * sigf(d3.y);
            ac2 += s0v.z * sigf(d0.z) + s1v.z * sigf(d1.z) + s2v.z * sigf(d2.z) + s3v.z * sigf(d3.z);
            ac3 += s0v.w * sigf(d0.w) + s1v.w * sigf(d1.w) + s2v.w * sigf(d2.w) + s3v.w * sigf(d3.w);
        } else {
            for (int e2 = lo; e2 < hi; e2++) {
                const float* rp = &rs[wid][e2 * 64];
                float4 sv = *(const float4*)&stIn[sj[wid][e2] * 64 + b0];
                float4 dd = {0,0,0,0};
#pragma unroll
                for (int k = 0; k < 64; k++) {
                    float4 mv = *(const float4*)&ms[k * 64 + b0];
                    float v = rp[k];
                    dd.x += mv.x * v; dd.y += mv.y * v; dd.z += mv.z * v; dd.w += mv.w * v;
                }
                ac0 += sv.x * sigf(dd.x); ac1 += sv.y * sigf(dd.y);
                ac2 += sv.z * sigf(dd.z); ac3 += sv.w * sigf(dd.w);
            }
        }
        __syncwarp();
    }
    ac0 += __shfl_down_sync(0xffffffffu, ac0, 16);
    ac1 += __shfl_down_sync(0xffffffffu, ac1, 16);
    ac2 += __shfl_down_sync(0xffffffffu, ac2, 16);
    ac3 += __shfl_down_sync(0xffffffffu, ac3, 16);
    if (lane < 16) {
        float4 res = {ac0, ac1, ac2, ac3};
        *(float4*)&stOut[o * 64 + b0] = res;
        int ob = t * SZ + o;
        out[(b0 + 0) * (LL * SZ) + ob] = ac0;
        out[(b0 + 1) * (LL * SZ) + ob] = ac1;
        out[(b0 + 2) * (LL * SZ) + ob] = ac2;
        out[(b0 + 3) * (LL * SZ) + ob] = ac3;
    }
}

extern "C" void kernel_launch(void* const* d_in, const int* in_sizes, int n_in,
                              void* d_out, int out_size) {
    const int*   x     = (const int*)d_in[0];
    const int*   rsub  = (const int*)d_in[1];
    const int*   robj  = (const int*)d_in[2];
    const float* aemb  = (const float*)d_in[3];
    const float* pemb  = (const float*)d_in[4];
    const float* semb  = (const float*)d_in[5];
    const float* w1    = (const float*)d_in[6];
    const float* b1    = (const float*)d_in[7];
    const float* w2    = (const float*)d_in[8];
    const float* b2    = (const float*)d_in[9];
    const float* qw    = (const float*)d_in[10];
    const float* qb    = (const float*)d_in[11];
    const float* mw1   = (const float*)d_in[12];
    const float* mb1   = (const float*)d_in[13];
    const float* mw2   = (const float*)d_in[14];
    const float* mb2   = (const float*)d_in[15];
    const float* minit = (const float*)d_in[16];
    float* out = (float*)d_out;

    k_zero<<<8, 256>>>();
    k_hist<<<256, 256>>>(robj);
    k_scan<<<1, 1024>>>();
    k_scatter<<<256, 256>>>(robj);
    k_bsort<<<256, 256>>>(rsub);
    k_p12<<<256, 256>>>(semb, w1);
    k_rel<<<2048, 128>>>(b1, w2, b2);
    k_meta<<<32, 256>>>(x, aemb, pemb, qw, qb, mw1, mb1, mw2, mb2, minit);
    k_init<<<512, 256>>>(x);
    for (int t = 0; t < LL; t++) {
        k_step<<<256, 256>>>(t, out);
    }
}

// round 4
// speedup vs baseline: 1.7278x; 1.7278x over previous
#include <cuda_runtime.h>

#define BB 64
#define SZ 2048
#define LL 16
#define AA 64
#define HH 256
#define RR 65536
#define XW (SZ + LL)

// ---------------- scratch (static device globals; no allocs) ----------------
__device__ __align__(16) float g_P1[SZ * HH];
__device__ __align__(16) float g_P2[SZ * HH];
__device__ __align__(16) float g_rel[RR * AA];          // relation rows, CSR-sorted order
__device__ __align__(16) float g_metaM[LL * BB * AA];   // [(t*64+b)][k]
__device__ __align__(16) float g_D[(size_t)LL * RR * BB]; // raw dots, [t][e][b]  (268MB)
__device__ __align__(16) float g_stateAll[LL + 1][SZ * BB]; // [t][o][b]
__device__ int g_perm[RR];
__device__ int g_subjS[RR];
__device__ int g_objS[RR];
__device__ int g_counts[SZ];
__device__ int g_rowptr[SZ + 1];
__device__ int g_offs[SZ];

// ---------------- tf32 mma helpers ----------------
__device__ __forceinline__ unsigned f2t(float f) {
    unsigned u;
    asm("cvt.rna.tf32.f32 %0, %1;" : "=r"(u) : "f"(f));
    return u;
}
__device__ __forceinline__ void mma8(float4& d, unsigned a0, unsigned a1, unsigned a2,
                                     unsigned a3, unsigned b0, unsigned b1) {
    asm volatile(
        "mma.sync.aligned.m16n8k8.row.col.f32.tf32.tf32.f32 "
        "{%0,%1,%2,%3},{%4,%5,%6,%7},{%8,%9},{%0,%1,%2,%3};"
        : "+f"(d.x), "+f"(d.y), "+f"(d.z), "+f"(d.w)
        : "r"(a0), "r"(a1), "r"(a2), "r"(a3), "r"(b0), "r"(b1));
}

__device__ __forceinline__ float sigf(float v) {
    return __fdividef(1.f, 1.f + __expf(-v));
}

// ---------------- CSR build (deterministic) ----------------
__global__ void k_zero() {
    int i = blockIdx.x * blockDim.x + threadIdx.x;
    if (i < SZ) g_counts[i] = 0;
}

__global__ void k_hist(const int* __restrict__ robj) {
    int e = blockIdx.x * blockDim.x + threadIdx.x;
    if (e < RR) atomicAdd(&g_counts[robj[e]], 1);
}

__global__ void k_scan() {  // 1 block, 1024 threads: scan of 2048
    __shared__ int sA[SZ], sB[SZ];
    int tid = threadIdx.x;
    for (int i = tid; i < SZ; i += 1024) sA[i] = g_counts[i];
    __syncthreads();
    int* src = sA; int* dst = sB;
    for (int off = 1; off < SZ; off <<= 1) {
        for (int i = tid; i < SZ; i += 1024)
            dst[i] = src[i] + (i >= off ? src[i - off] : 0);
        __syncthreads();
        int* t = src; src = dst; dst = t;
    }
    for (int i = tid; i < SZ; i += 1024) {
        g_rowptr[i + 1] = src[i];
        g_offs[i] = (i == 0) ? 0 : src[i - 1];
    }
    if (tid == 0) g_rowptr[0] = 0;
}

__global__ void k_scatter(const int* __restrict__ robj) {
    int e = blockIdx.x * blockDim.x + threadIdx.x;
    if (e < RR) {
        int pos = atomicAdd(&g_offs[robj[e]], 1);
        g_perm[pos] = e;
    }
}

// sort each bucket's edge ids ascending (determinism), emit subj/obj in sorted order
__global__ void k_bsort(const int* __restrict__ rsub) {
    __shared__ int buf[8][208];
    int wid = threadIdx.x >> 5, lane = threadIdx.x & 31;
    int o = blockIdx.x * 8 + wid;
    int s = g_rowptr[o], e = g_rowptr[o + 1], n = e - s;
    if (n > 0 && n <= 208) {
        for (int i = lane; i < n; i += 32) buf[wid][i] = g_perm[s + i];
        __syncwarp();
        for (int r = 0; r < n; r++) {           // odd-even transposition
            int par = r & 1;
            for (int i = par + 2 * lane; i + 1 < n; i += 64) {
                int a = buf[wid][i], b = buf[wid][i + 1];
                if (a > b) { buf[wid][i] = b; buf[wid][i + 1] = a; }
            }
            __syncwarp();
        }
        for (int i = lane; i < n; i += 32) {
            int p = buf[wid][i];
            g_perm[s + i] = p;
            g_subjS[s + i] = rsub[p];
            g_objS[s + i] = o;
        }
    } else {
        for (int i = lane; i < n; i += 32) {
            int p = g_perm[s + i];
            g_subjS[s + i] = rsub[p];
            g_objS[s + i] = o;
        }
    }
}

// ---------------- P1/P2 = state_emb @ W1 halves ----------------
__global__ void k_p12(const float* __restrict__ emb, const float* __restrict__ w1) {
    __shared__ float es[8][64];
    int tid = threadIdx.x;
    int r0 = blockIdx.x * 8;
    for (int i = tid; i < 512; i += 256) es[i >> 6][i & 63] = emb[r0 * 64 + i];
    __syncthreads();
    float a1[8], a2[8];
#pragma unroll
    for (int r = 0; r < 8; r++) { a1[r] = 0.f; a2[r] = 0.f; }
    for (int k = 0; k < 64; k++) {
        float wa = w1[k * HH + tid];
        float wb = w1[(64 + k) * HH + tid];
#pragma unroll
        for (int r = 0; r < 8; r++) {
            a1[r] += es[r][k] * wa;
            a2[r] += es[r][k] * wb;
        }
    }
#pragma unroll
    for (int r = 0; r < 8; r++) {
        g_P1[(r0 + r) * HH + tid] = a1[r];
        g_P2[(r0 + r) * HH + tid] = a2[r];
    }
}

// ---------------- relation rows via tf32 mma ----------------
// block: 64 edges, N=64, K=256 in 4 chunks of 64. 256 threads = 8 warps (4m x 2n).
__global__ void k_rel2(const float* __restrict__ b1v, const float* __restrict__ w2,
                       const float* __restrict__ b2v) {
    __shared__ float hs[64][68];
    __shared__ float ws[64][68];
    __shared__ int ssub[64], sobj[64];
    int tid = threadIdx.x;
    int e0 = blockIdx.x * 64;
    if (tid < 64) { ssub[tid] = g_subjS[e0 + tid]; sobj[tid] = g_objS[e0 + tid]; }
    __syncthreads();
    int warp = tid >> 5, lane = tid & 31;
    int wm = warp & 3, wn = warp >> 2;
    int g = lane >> 2, tg = lane & 3;
    int r0 = wm * 16, n0 = wn * 32;
    float4 acc[4] = {};
    for (int kc = 0; kc < 4; kc++) {
        // fill hidden chunk + W2 chunk
        for (int i = tid; i < 64 * 16; i += 256) {
            int r = i >> 4, c = (i & 15) * 4;
            float4 p1 = *(const float4*)&g_P1[ssub[r] * HH + kc * 64 + c];
            float4 p2 = *(const float4*)&g_P2[sobj[r] * HH + kc * 64 + c];
            float4 bb = *(const float4*)&b1v[kc * 64 + c];
            float4 h;
            h.x = fmaxf(p1.x + p2.x + bb.x, 0.f);
            h.y = fmaxf(p1.y + p2.y + bb.y, 0.f);
            h.z = fmaxf(p1.z + p2.z + bb.z, 0.f);
            h.w = fmaxf(p1.w + p2.w + bb.w, 0.f);
            *(float4*)&hs[r][c] = h;
            *(float4*)&ws[r][c] = *(const float4*)&w2[(kc * 64 + r) * 64 + c];
        }
        __syncthreads();
#pragma unroll
        for (int ks = 0; ks < 8; ks++) {
            int kk = ks * 8;
            unsigned a0 = f2t(hs[r0 + g][kk + tg]);
            unsigned a1 = f2t(hs[r0 + g + 8][kk + tg]);
            unsigned a2 = f2t(hs[r0 + g][kk + tg + 4]);
            unsigned a3 = f2t(hs[r0 + g + 8][kk + tg + 4]);
#pragma unroll
            for (int nf = 0; nf < 4; nf++) {
                int n = n0 + nf * 8 + g;
                unsigned b0 = f2t(ws[kk + tg][n]);
                unsigned b1 = f2t(ws[kk + tg + 4][n]);
                mma8(acc[nf], a0, a1, a2, a3, b0, b1);
            }
        }
        __syncthreads();
    }
#pragma unroll
    for (int nf = 0; nf < 4; nf++) {
        int col = n0 + nf * 8 + 2 * tg;
        float bx = b2v[col], by = b2v[col + 1];
        int row = e0 + r0 + g;
        float2 v0 = {acc[nf].x + bx, acc[nf].y + by};
        float2 v1 = {acc[nf].z + bx, acc[nf].w + by};
        *(float2*)&g_rel[row * 64 + col] = v0;
        *(float2*)&g_rel[(row + 8) * 64 + col] = v1;
    }
}

// ---------------- meta recurrence: 32 blocks x (2 batches x 128 threads) ----------------
__global__ void k_meta(const int* __restrict__ x, const float* __restrict__ aemb,
                       const float* __restrict__ pemb, const float* __restrict__ qw,
                       const float* __restrict__ qb, const float* __restrict__ mw1,
                       const float* __restrict__ mb1, const float* __restrict__ mw2,
                       const float* __restrict__ mb2, const float* __restrict__ minit) {
    __shared__ float sent[2][16][128];
    __shared__ float meta[2][64];
    __shared__ float query[2][128];
    __shared__ float attn[2][16];
    __shared__ float z[2][192];
    __shared__ float hid[2][256];
    int tid = threadIdx.x;
    int g = tid >> 7, t = tid & 127;
    int b = blockIdx.x * 2 + g;
    for (int l = 0; l < 16; l++) {
        int a = x[b * XW + SZ + l];
        sent[g][l][t] = (t < 64) ? aemb[a * 64 + t] : pemb[l * 64 + (t - 64)];
    }
    if (t < 64) meta[g][t] = minit[t];
    __syncthreads();
    for (int st = 0; st < 16; st++) {
        float q = qb[t];
        for (int k = 0; k < 64; k++) q += meta[g][k] * qw[k * 128 + t];
        query[g][t] = q;
        __syncthreads();
        if (t < 16) {
            float sc = 0.f;
            for (int d = 0; d < 128; d++) sc += query[g][d] * sent[g][t][d];
            attn[g][t] = sc;
        }
        __syncthreads();
        if (t == 0) {
            float m = attn[g][0];
            for (int l = 1; l < 16; l++) m = fmaxf(m, attn[g][l]);
            float ev[16], ssum = 0.f;
            for (int l = 0; l < 16; l++) { ev[l] = __expf(attn[g][l] - m); ssum += ev[l]; }
            for (int l = 0; l < 16; l++) attn[g][l] = ev[l] / ssum;
        }
        __syncthreads();
        {
            float at = 0.f;
            for (int l = 0; l < 16; l++) at += attn[g][l] * sent[g][l][t];
            z[g][64 + t] = at;
            if (t < 64) z[g][t] = meta[g][t];
        }
        __syncthreads();
        {
            float h0 = mb1[t], h1 = mb1[t + 128];
            for (int k = 0; k < 192; k++) {
                float zv = z[g][k];
                h0 += zv * mw1[k * HH + t];
                h1 += zv * mw1[k * HH + t + 128];
            }
            hid[g][t] = fmaxf(h0, 0.f);
            hid[g][t + 128] = fmaxf(h1, 0.f);
        }
        __syncthreads();
        if (t < 64) {
            float m = mb2[t];
            for (int k = 0; k < 256; k++) m += hid[g][k] * mw2[k * 64 + t];
            g_metaM[(st * 64 + b) * 64 + t] = m;  // [(t,b)][k]
            meta[g][t] = m;
        }
        __syncthreads();
    }
}

// ---------------- big dots GEMM: D[t][e][b] = rel[e] . meta_t[b] (tf32 mma) -------
// grid (1024, 16): block = 64 edges x 64 cols (one t), K=64. 256 threads (4m x 2n warps).
__global__ void k_dots() {
    __shared__ float sA[64][68];
    __shared__ float sB[64][68];
    int tid = threadIdx.x;
    int e0 = blockIdx.x * 64;
    int c0 = blockIdx.y * 64;  // t = blockIdx.y
    for (int i = tid; i < 64 * 16; i += 256) {
        int r = i >> 4, c = (i & 15) * 4;
        *(float4*)&sA[r][c] = *(const float4*)&g_rel[(e0 + r) * 64 + c];
        *(float4*)&sB[r][c] = *(const float4*)&g_metaM[(c0 + r) * 64 + c];
    }
    __syncthreads();
    int warp = tid >> 5, lane = tid & 31;
    int wm = warp & 3, wn = warp >> 2;
    int g = lane >> 2, tg = lane & 3;
    int r0 = wm * 16, n0 = wn * 32;
    float4 acc[4] = {};
#pragma unroll
    for (int ks = 0; ks < 8; ks++) {
        int kk = ks * 8;
        unsigned a0 = f2t(sA[r0 + g][kk + tg]);
        unsigned a1 = f2t(sA[r0 + g + 8][kk + tg]);
        unsigned a2 = f2t(sA[r0 + g][kk + tg + 4]);
        unsigned a3 = f2t(sA[r0 + g + 8][kk + tg + 4]);
#pragma unroll
        for (int nf = 0; nf < 4; nf++) {
            int n = n0 + nf * 8 + g;
            unsigned b0 = f2t(sB[n][kk + tg]);
            unsigned b1 = f2t(sB[n][kk + tg + 4]);
            mma8(acc[nf], a0, a1, a2, a3, b0, b1);
        }
    }
    float* Dt = g_D + (size_t)blockIdx.y * (RR * 64);
#pragma unroll
    for (int nf = 0; nf < 4; nf++) {
        int col = n0 + nf * 8 + 2 * tg;
        int row = e0 + r0 + g;
        float2 v0 = {acc[nf].x, acc[nf].y};
        float2 v1 = {acc[nf].z, acc[nf].w};
        *(float2*)&Dt[row * 64 + col] = v0;
        *(float2*)&Dt[(row + 8) * 64 + col] = v1;
    }
}

// ---------------- init transposed state ----------------
__global__ void k_init(const int* __restrict__ x) {
    int i = blockIdx.x * blockDim.x + threadIdx.x;  // 131072
    int b = i >> 11, o = i & 2047;
    g_stateAll[0][o * 64 + b] = (float)x[b * XW + o];
}

// ---------------- one propagation step: memory-bound gather-reduce ----------------
__global__ void k_step2(int t) {
    const float* __restrict__ stIn = g_stateAll[t];
    float* __restrict__ stOut = g_stateAll[t + 1];
    const float* __restrict__ Dt = g_D + (size_t)t * (RR * 64);
    int tid = threadIdx.x, wid = tid >> 5, lane = tid & 31;
    int o = blockIdx.x * 8 + wid;
    int s0 = g_rowptr[o], s1 = g_rowptr[o + 1];
    int b0 = lane * 2;
    float ax = 0.f, ay = 0.f;
    int e = s0;
    for (; e + 4 <= s1; e += 4) {
        int j0 = g_subjS[e], j1 = g_subjS[e + 1], j2 = g_subjS[e + 2], j3 = g_subjS[e + 3];
        float2 d0 = *(const float2*)&Dt[(e + 0) * 64 + b0];
        float2 d1 = *(const float2*)&Dt[(e + 1) * 64 + b0];
        float2 d2 = *(const float2*)&Dt[(e + 2) * 64 + b0];
        float2 d3 = *(const float2*)&Dt[(e + 3) * 64 + b0];
        float2 s0v = *(const float2*)&stIn[j0 * 64 + b0];
        float2 s1v = *(const float2*)&stIn[j1 * 64 + b0];
        float2 s2v = *(const float2*)&stIn[j2 * 64 + b0];
        float2 s3v = *(const float2*)&stIn[j3 * 64 + b0];
        ax += s0v.x * sigf(d0.x) + s1v.x * sigf(d1.x) + s2v.x * sigf(d2.x) + s3v.x * sigf(d3.x);
        ay += s0v.y * sigf(d0.y) + s1v.y * sigf(d1.y) + s2v.y * sigf(d2.y) + s3v.y * sigf(d3.y);
    }
    for (; e < s1; e++) {
        int j = g_subjS[e];
        float2 d = *(const float2*)&Dt[e * 64 + b0];
        float2 s = *(const float2*)&stIn[j * 64 + b0];
        ax += s.x * sigf(d.x);
        ay += s.y * sigf(d.y);
    }
    float2 res = {ax, ay};
    *(float2*)&stOut[o * 64 + b0] = res;
}

// ---------------- final transpose: out[b][t][o] = stateAll[t+1][o][b] -------------
__global__ void k_out(float* __restrict__ out) {
    __shared__ float tile[64][65];
    int t = blockIdx.x, o0 = blockIdx.y * 64;
    const float* st = g_stateAll[t + 1];
    for (int i = threadIdx.x; i < 64 * 64; i += 256) {
        int r = i >> 6, b = i & 63;
        tile[b][r] = st[(o0 + r) * 64 + b];
    }
    __syncthreads();
    for (int i = threadIdx.x; i < 64 * 64; i += 256) {
        int b = i >> 6, c = i & 63;
        out[(size_t)b * (LL * SZ) + t * SZ + o0 + c] = tile[b][c];
    }
}

extern "C" void kernel_launch(void* const* d_in, const int* in_sizes, int n_in,
                              void* d_out, int out_size) {
    const int*   x     = (const int*)d_in[0];
    const int*   rsub  = (const int*)d_in[1];
    const int*   robj  = (const int*)d_in[2];
    const float* aemb  = (const float*)d_in[3];
    const float* pemb  = (const float*)d_in[4];
    const float* semb  = (const float*)d_in[5];
    const float* w1    = (const float*)d_in[6];
    const float* b1    = (const float*)d_in[7];
    const float* w2    = (const float*)d_in[8];
    const float* b2    = (const float*)d_in[9];
    const float* qw    = (const float*)d_in[10];
    const float* qb    = (const float*)d_in[11];
    const float* mw1   = (const float*)d_in[12];
    const float* mb1   = (const float*)d_in[13];
    const float* mw2   = (const float*)d_in[14];
    const float* mb2   = (const float*)d_in[15];
    const float* minit = (const float*)d_in[16];
    float* out = (float*)d_out;

    k_zero<<<8, 256>>>();
    k_hist<<<256, 256>>>(robj);
    k_scan<<<1, 1024>>>();
    k_scatter<<<256, 256>>>(robj);
    k_bsort<<<256, 256>>>(rsub);
    k_p12<<<256, 256>>>(semb, w1);
    k_meta<<<32, 256>>>(x, aemb, pemb, qw, qb, mw1, mb1, mw2, mb2, minit);
    k_rel2<<<1024, 256>>>(b1, w2, b2);
    k_dots<<<dim3(1024, 16), 256>>>();
    k_init<<<512, 256>>>(x);
    for (int t = 0; t < LL; t++) {
        k_step2<<<256, 256>>>(t);
    }
    k_out<<<dim3(16, 32), 256>>>(out);
}

// round 5
// speedup vs baseline: 1.8546x; 1.0734x over previous
#include <cuda_runtime.h>

#define BB 64
#define SZ 2048
#define LL 16
#define AA 64
#define HH 256
#define RR 65536
#define XW (SZ + LL)
#define BPB 4   // buckets per step-block -> 512 blocks

// ---------------- scratch (static device globals; no allocs) ----------------
__device__ __align__(16) float    g_P1[SZ * HH];
__device__ __align__(16) float    g_P2[SZ * HH];
__device__ __align__(16) unsigned g_relT[RR * AA];        // relation rows as tf32 bits, CSR order
__device__ __align__(16) unsigned g_metaT32[LL * BB * AA]; // tf32 bits, [(t*64+b)][k]
__device__ __align__(16) float    g_stateAll[LL + 1][SZ * BB]; // [t][o][b]
__device__ int g_perm[RR];
__device__ int g_subjS[RR];
__device__ int g_objS[RR];
__device__ int g_counts[SZ];
__device__ int g_rowptr[SZ + 1];
__device__ int g_offs[SZ];

// ---------------- tf32 mma helpers ----------------
__device__ __forceinline__ unsigned f2t(float f) {
    unsigned u;
    asm("cvt.rna.tf32.f32 %0, %1;" : "=r"(u) : "f"(f));
    return u;
}
__device__ __forceinline__ void mma8(float4& d, unsigned a0, unsigned a1, unsigned a2,
                                     unsigned a3, unsigned b0, unsigned b1) {
    asm volatile(
        "mma.sync.aligned.m16n8k8.row.col.f32.tf32.tf32.f32 "
        "{%0,%1,%2,%3},{%4,%5,%6,%7},{%8,%9},{%0,%1,%2,%3};"
        : "+f"(d.x), "+f"(d.y), "+f"(d.z), "+f"(d.w)
        : "r"(a0), "r"(a1), "r"(a2), "r"(a3), "r"(b0), "r"(b1));
}

__device__ __forceinline__ float sigf(float v) {
    return __fdividef(1.f, 1.f + __expf(-v));
}

// ---------------- CSR build (deterministic) ----------------
__global__ void k_zero() {
    int i = blockIdx.x * blockDim.x + threadIdx.x;
    if (i < SZ) g_counts[i] = 0;
}

__global__ void k_hist(const int* __restrict__ robj) {
    int e = blockIdx.x * blockDim.x + threadIdx.x;
    if (e < RR) atomicAdd(&g_counts[robj[e]], 1);
}

__global__ void k_scan() {  // 1 block, 1024 threads: scan of 2048
    __shared__ int sA[SZ], sB[SZ];
    int tid = threadIdx.x;
    for (int i = tid; i < SZ; i += 1024) sA[i] = g_counts[i];
    __syncthreads();
    int* src = sA; int* dst = sB;
    for (int off = 1; off < SZ; off <<= 1) {
        for (int i = tid; i < SZ; i += 1024)
            dst[i] = src[i] + (i >= off ? src[i - off] : 0);
        __syncthreads();
        int* t = src; src = dst; dst = t;
    }
    for (int i = tid; i < SZ; i += 1024) {
        g_rowptr[i + 1] = src[i];
        g_offs[i] = (i == 0) ? 0 : src[i - 1];
    }
    if (tid == 0) g_rowptr[0] = 0;
}

__global__ void k_scatter(const int* __restrict__ robj) {
    int e = blockIdx.x * blockDim.x + threadIdx.x;
    if (e < RR) {
        int pos = atomicAdd(&g_offs[robj[e]], 1);
        g_perm[pos] = e;
    }
}

// sort each bucket's edge ids ascending (determinism), emit subj/obj in sorted order
__global__ void k_bsort(const int* __restrict__ rsub) {
    __shared__ int buf[8][208];
    int wid = threadIdx.x >> 5, lane = threadIdx.x & 31;
    int o = blockIdx.x * 8 + wid;
    int s = g_rowptr[o], e = g_rowptr[o + 1], n = e - s;
    if (n > 0 && n <= 208) {
        for (int i = lane; i < n; i += 32) buf[wid][i] = g_perm[s + i];
        __syncwarp();
        for (int r = 0; r < n; r++) {           // odd-even transposition
            int par = r & 1;
            for (int i = par + 2 * lane; i + 1 < n; i += 64) {
                int a = buf[wid][i], b = buf[wid][i + 1];
                if (a > b) { buf[wid][i] = b; buf[wid][i + 1] = a; }
            }
            __syncwarp();
        }
        for (int i = lane; i < n; i += 32) {
            int p = buf[wid][i];
            g_perm[s + i] = p;
            g_subjS[s + i] = rsub[p];
            g_objS[s + i] = o;
        }
    } else {
        for (int i = lane; i < n; i += 32) {
            int p = g_perm[s + i];
            g_subjS[s + i] = rsub[p];
            g_objS[s + i] = o;
        }
    }
}

// ---------------- P1/P2 = state_emb @ W1 halves ----------------
__global__ void k_p12(const float* __restrict__ emb, const float* __restrict__ w1) {
    __shared__ float es[8][64];
    int tid = threadIdx.x;
    int r0 = blockIdx.x * 8;
    for (int i = tid; i < 512; i += 256) es[i >> 6][i & 63] = emb[r0 * 64 + i];
    __syncthreads();
    float a1[8], a2[8];
#pragma unroll
    for (int r = 0; r < 8; r++) { a1[r] = 0.f; a2[r] = 0.f; }
    for (int k = 0; k < 64; k++) {
        float wa = w1[k * HH + tid];
        float wb = w1[(64 + k) * HH + tid];
#pragma unroll
        for (int r = 0; r < 8; r++) {
            a1[r] += es[r][k] * wa;
            a2[r] += es[r][k] * wb;
        }
    }
#pragma unroll
    for (int r = 0; r < 8; r++) {
        g_P1[(r0 + r) * HH + tid] = a1[r];
        g_P2[(r0 + r) * HH + tid] = a2[r];
    }
}

// ---------------- relation rows via tf32 mma; output tf32 bits ----------------
// block: 64 edges, N=64, K=256 in 4 chunks of 64. 256 threads = 8 warps (4m x 2n).
__global__ void k_rel2(const float* __restrict__ b1v, const float* __restrict__ w2,
                       const float* __restrict__ b2v) {
    __shared__ float hs[64][68];
    __shared__ float ws[64][68];
    __shared__ int ssub[64], sobj[64];
    int tid = threadIdx.x;
    int e0 = blockIdx.x * 64;
    if (tid < 64) { ssub[tid] = g_subjS[e0 + tid]; sobj[tid] = g_objS[e0 + tid]; }
    __syncthreads();
    int warp = tid >> 5, lane = tid & 31;
    int wm = warp & 3, wn = warp >> 2;
    int g = lane >> 2, tg = lane & 3;
    int r0 = wm * 16, n0 = wn * 32;
    float4 acc[4] = {};
    for (int kc = 0; kc < 4; kc++) {
        for (int i = tid; i < 64 * 16; i += 256) {
            int r = i >> 4, c = (i & 15) * 4;
            float4 p1 = *(const float4*)&g_P1[ssub[r] * HH + kc * 64 + c];
            float4 p2 = *(const float4*)&g_P2[sobj[r] * HH + kc * 64 + c];
            float4 bb = *(const float4*)&b1v[kc * 64 + c];
            float4 h;
            h.x = fmaxf(p1.x + p2.x + bb.x, 0.f);
            h.y = fmaxf(p1.y + p2.y + bb.y, 0.f);
            h.z = fmaxf(p1.z + p2.z + bb.z, 0.f);
            h.w = fmaxf(p1.w + p2.w + bb.w, 0.f);
            *(float4*)&hs[r][c] = h;
            *(float4*)&ws[r][c] = *(const float4*)&w2[(kc * 64 + r) * 64 + c];
        }
        __syncthreads();
#pragma unroll
        for (int ks = 0; ks < 8; ks++) {
            int kk = ks * 8;
            unsigned a0 = f2t(hs[r0 + g][kk + tg]);
            unsigned a1 = f2t(hs[r0 + g + 8][kk + tg]);
            unsigned a2 = f2t(hs[r0 + g][kk + tg + 4]);
            unsigned a3 = f2t(hs[r0 + g + 8][kk + tg + 4]);
#pragma unroll
            for (int nf = 0; nf < 4; nf++) {
                int n = n0 + nf * 8 + g;
                unsigned b0 = f2t(ws[kk + tg][n]);
                unsigned b1 = f2t(ws[kk + tg + 4][n]);
                mma8(acc[nf], a0, a1, a2, a3, b0, b1);
            }
        }
        __syncthreads();
    }
#pragma unroll
    for (int nf = 0; nf < 4; nf++) {
        int col = n0 + nf * 8 + 2 * tg;
        float bx = b2v[col], by = b2v[col + 1];
        int row = e0 + r0 + g;
        uint2 v0 = {f2t(acc[nf].x + bx), f2t(acc[nf].y + by)};
        uint2 v1 = {f2t(acc[nf].z + bx), f2t(acc[nf].w + by)};
        *(uint2*)&g_relT[row * 64 + col] = v0;
        *(uint2*)&g_relT[(row + 8) * 64 + col] = v1;
    }
}

// ---------------- meta recurrence: 32 blocks x (2 batches x 128 threads) ----------------
__global__ void k_meta(const int* __restrict__ x, const float* __restrict__ aemb,
                       const float* __restrict__ pemb, const float* __restrict__ qw,
                       const float* __restrict__ qb, const float* __restrict__ mw1,
                       const float* __restrict__ mb1, const float* __restrict__ mw2,
                       const float* __restrict__ mb2, const float* __restrict__ minit) {
    __shared__ float sent[2][16][128];
    __shared__ float meta[2][64];
    __shared__ float query[2][128];
    __shared__ float attn[2][16];
    __shared__ float z[2][192];
    __shared__ float hid[2][256];
    int tid = threadIdx.x;
    int g = tid >> 7, t = tid & 127;
    int b = blockIdx.x * 2 + g;
    for (int l = 0; l < 16; l++) {
        int a = x[b * XW + SZ + l];
        sent[g][l][t] = (t < 64) ? aemb[a * 64 + t] : pemb[l * 64 + (t - 64)];
    }
    if (t < 64) meta[g][t] = minit[t];
    __syncthreads();
    for (int st = 0; st < 16; st++) {
        float q = qb[t];
        for (int k = 0; k < 64; k++) q += meta[g][k] * qw[k * 128 + t];
        query[g][t] = q;
        __syncthreads();
        if (t < 16) {
            float sc = 0.f;
            for (int d = 0; d < 128; d++) sc += query[g][d] * sent[g][t][d];
            attn[g][t] = sc;
        }
        __syncthreads();
        if (t == 0) {
            float m = attn[g][0];
            for (int l = 1; l < 16; l++) m = fmaxf(m, attn[g][l]);
            float ev[16], ssum = 0.f;
            for (int l = 0; l < 16; l++) { ev[l] = __expf(attn[g][l] - m); ssum += ev[l]; }
            for (int l = 0; l < 16; l++) attn[g][l] = ev[l] / ssum;
        }
        __syncthreads();
        {
            float at = 0.f;
            for (int l = 0; l < 16; l++) at += attn[g][l] * sent[g][l][t];
            z[g][64 + t] = at;
            if (t < 64) z[g][t] = meta[g][t];
        }
        __syncthreads();
        {
            float h0 = mb1[t], h1 = mb1[t + 128];
            for (int k = 0; k < 192; k++) {
                float zv = z[g][k];
                h0 += zv * mw1[k * HH + t];
                h1 += zv * mw1[k * HH + t + 128];
            }
            hid[g][t] = fmaxf(h0, 0.f);
            hid[g][t + 128] = fmaxf(h1, 0.f);
        }
        __syncthreads();
        if (t < 64) {
            float m = mb2[t];
            for (int k = 0; k < 256; k++) m += hid[g][k] * mw2[k * 64 + t];
            g_metaT32[(st * 64 + b) * 64 + t] = f2t(m);  // [(t,b)][k] tf32 bits
            meta[g][t] = m;
        }
        __syncthreads();
    }
}

// ---------------- init transposed state ----------------
__global__ void k_init(const int* __restrict__ x) {
    int i = blockIdx.x * blockDim.x + threadIdx.x;  // 131072
    int b = i >> 11, o = i & 2047;
    g_stateAll[0][o * 64 + b] = (float)x[b * XW + o];
}

// ---------------- fused step: MMA dots + sigmoid + gather + segmented reduce ------
// block = 4 buckets (512 blocks), 256 threads = 8 warps (4m x 2n) over 64x64 tiles.
__global__ void __launch_bounds__(256) k_stepF(int t) {
    __shared__ __align__(16) unsigned tileBuf[64 * 68];  // rel tf32 bits, reused as prod floats
    __shared__ __align__(16) unsigned metaS[64 * 68];
    __shared__ float acc[(BPB + 1) * 64];
    __shared__ int ssubj[64];
    __shared__ unsigned char rowb[64];
    const float* __restrict__ stIn = g_stateAll[t];
    float* __restrict__ stOut = g_stateAll[t + 1];
    int tid = threadIdx.x;
    int bkt0 = blockIdx.x * BPB;
    int eStart = g_rowptr[bkt0];
    int eEnd = g_rowptr[bkt0 + BPB];

    const unsigned* mt = &g_metaT32[t * 64 * 64];
    for (int i = tid; i < 64 * 16; i += 256) {
        int r = i >> 4, c = (i & 15) * 4;
        *(uint4*)&metaS[r * 68 + c] = *(const uint4*)&mt[r * 64 + c];
    }
    for (int i = tid; i < (BPB + 1) * 64; i += 256) acc[i] = 0.f;
    __syncthreads();

    int warp = tid >> 5, lane = tid & 31;
    int wm = warp & 3, wn = warp >> 2;
    int g = lane >> 2, tg = lane & 3;
    int r0 = wm * 16, n0 = wn * 32;
    int q = tid >> 6, col = tid & 63;

    for (int base = eStart; base < eEnd; base += 64) {
        int m = min(64, eEnd - base);
        // fill rel tile (tf32 bits) + subj + local bucket ids
        for (int i = tid; i < 64 * 16; i += 256) {
            int r = i >> 4, c = (i & 15) * 4;
            uint4 v = (r < m) ? *(const uint4*)&g_relT[(base + r) * 64 + c]
                              : make_uint4(0u, 0u, 0u, 0u);
            *(uint4*)&tileBuf[r * 68 + c] = v;
        }
        if (tid < 64) {
            if (tid < m) {
                ssubj[tid] = g_subjS[base + tid];
                rowb[tid] = (unsigned char)(g_objS[base + tid] - bkt0);
            } else { ssubj[tid] = 0; rowb[tid] = BPB; }
        }
        __syncthreads();

        float4 accf[4] = {};
#pragma unroll
        for (int ks = 0; ks < 8; ks++) {
            int kk = ks * 8;
            unsigned a0 = tileBuf[(r0 + g) * 68 + kk + tg];
            unsigned a1 = tileBuf[(r0 + g + 8) * 68 + kk + tg];
            unsigned a2 = tileBuf[(r0 + g) * 68 + kk + tg + 4];
            unsigned a3 = tileBuf[(r0 + g + 8) * 68 + kk + tg + 4];
#pragma unroll
            for (int nf = 0; nf < 4; nf++) {
                int n = n0 + nf * 8 + g;
                unsigned b0 = metaS[n * 68 + kk + tg];
                unsigned b1 = metaS[n * 68 + kk + tg + 4];
                mma8(accf[nf], a0, a1, a2, a3, b0, b1);
            }
        }
        __syncthreads();  // everyone done reading tileBuf as rel

        // epilogue: prod[e][b] = state[subj[e]][b] * sigmoid(D[e][b]) into tileBuf
        float* prod = (float*)tileBuf;
        int rA = r0 + g, rB = rA + 8;
        int sjA = ssubj[rA], sjB = ssubj[rB];
#pragma unroll
        for (int nf = 0; nf < 4; nf++) {
            int c = n0 + nf * 8 + 2 * tg;
            float2 svA = *(const float2*)&stIn[sjA * 64 + c];
            float2 svB = *(const float2*)&stIn[sjB * 64 + c];
            float2 pA = {svA.x * sigf(accf[nf].x), svA.y * sigf(accf[nf].y)};
            float2 pB = {svB.x * sigf(accf[nf].z), svB.y * sigf(accf[nf].w)};
            *(float2*)&prod[rA * 68 + c] = pA;
            *(float2*)&prod[rB * 68 + c] = pB;
        }
        __syncthreads();

        // segmented reduction: thread (q, col) sums rows [16q,16q+16) by bucket
        {
            float s = 0.f;
            int cur = rowb[q * 16];
#pragma unroll
            for (int r = q * 16; r < q * 16 + 16; r++) {
                int lb = rowb[r];
                if (lb != cur) { atomicAdd(&acc[cur * 64 + col], s); s = 0.f; cur = lb; }
                s += prod[r * 68 + col];
            }
            atomicAdd(&acc[cur * 64 + col], s);
        }
        __syncthreads();
    }

    for (int i = tid; i < BPB * 64; i += 256) {
        int lb = i >> 6, c = i & 63;
        stOut[(bkt0 + lb) * 64 + c] = acc[lb * 64 + c];
    }
}

// ---------------- final transpose: out[b][t][o] = stateAll[t+1][o][b] -------------
__global__ void k_out(float* __restrict__ out) {
    __shared__ float tile[64][65];
    int t = blockIdx.x, o0 = blockIdx.y * 64;
    const float* st = g_stateAll[t + 1];
    for (int i = threadIdx.x; i < 64 * 64; i += 256) {
        int r = i >> 6, b = i & 63;
        tile[b][r] = st[(o0 + r) * 64 + b];
    }
    __syncthreads();
    for (int i = threadIdx.x; i < 64 * 64; i += 256) {
        int b = i >> 6, c = i & 63;
        out[(size_t)b * (LL * SZ) + t * SZ + o0 + c] = tile[b][c];
    }
}

extern "C" void kernel_launch(void* const* d_in, const int* in_sizes, int n_in,
                              void* d_out, int out_size) {
    const int*   x     = (const int*)d_in[0];
    const int*   rsub  = (const int*)d_in[1];
    const int*   robj  = (const int*)d_in[2];
    const float* aemb  = (const float*)d_in[3];
    const float* pemb  = (const float*)d_in[4];
    const float* semb  = (const float*)d_in[5];
    const float* w1    = (const float*)d_in[6];
    const float* b1    = (const float*)d_in[7];
    const float* w2    = (const float*)d_in[8];
    const float* b2    = (const float*)d_in[9];
    const float* qw    = (const float*)d_in[10];
    const float* qb    = (const float*)d_in[11];
    const float* mw1   = (const float*)d_in[12];
    const float* mb1   = (const float*)d_in[13];
    const float* mw2   = (const float*)d_in[14];
    const float* mb2   = (const float*)d_in[15];
    const float* minit = (const float*)d_in[16];
    float* out = (float*)d_out;

    k_zero<<<8, 256>>>();
    k_hist<<<256, 256>>>(robj);
    k_scan<<<1, 1024>>>();
    k_scatter<<<256, 256>>>(robj);
    k_bsort<<<256, 256>>>(rsub);
    k_p12<<<256, 256>>>(semb, w1);
    k_meta<<<32, 256>>>(x, aemb, pemb, qw, qb, mw1, mb1, mw2, mb2, minit);
    k_rel2<<<1024, 256>>>(b1, w2, b2);
    k_init<<<512, 256>>>(x);
    for (int t = 0; t < LL; t++) {
        k_stepF<<<512, 256>>>(t);
    }
    k_out<<<dim3(16, 32), 256>>>(out);
}